// round 8
// baseline (speedup 1.0000x reference)
#include <cuda_runtime.h>

#define TS 32
#define HALO 5
#define IT 42                 // cols per tile buffer
#define ITR 44                // rows padded for 8-row-group overhang
#define NT 256
#define HI 1024
#define WI 1024
#define HW (HI*WI)
#define NPIX (8*3*HW)         // 25165824
#define NTHUMB (8*3*256*256)  // 1572864

typedef unsigned long long u64;

__device__ __forceinline__ u64 pack2(float lo, float hi){
    u64 d;
    asm("mov.b64 %0, {%1, %2};" : "=l"(d)
        : "r"(__float_as_uint(lo)), "r"(__float_as_uint(hi)));
    return d;
}
__device__ __forceinline__ void unpack2(u64 v, float &lo, float &hi){
    unsigned a, b;
    asm("mov.b64 {%0, %1}, %2;" : "=r"(a), "=r"(b) : "l"(v));
    lo = __uint_as_float(a); hi = __uint_as_float(b);
}
__device__ __forceinline__ u64 fma2(u64 a, u64 b, u64 c){
    u64 d;
    asm("fma.rn.f32x2 %0, %1, %2, %3;" : "=l"(d) : "l"(a), "l"(b), "l"(c));
    return d;
}
__device__ __forceinline__ float lk(float v){ return fmaxf(v, 0.2f*v); } // exact leaky

struct SM {
    float a[3][ITR][IT];      // [ch][row][col] 22176 B
    float b[3][ITR][IT];      //                22176 B
    u64   wsp[5][3][3][9];    // splatted conv3 weights {w,w} [S][o][i][kh*3+kw]
    u64   bsp[5][3];          // splatted biases
    float ftail[72];          // feat[420..491]
};                            // 47904 B static

// One residual 3x3 block: dst = leaky(src + conv3x3(src)), zero-masked to image.
// Thread owns a 1-col x 8-row strip = 4 vertical f32x2 pairs. Weight LDS.64
// amortize over 8 px. Row-group base clamped to keep all reads < ITR;
// overlapping groups rewrite identical values (benign).
template<int S, bool EDGE>
__device__ __forceinline__ void stage(const float (&src)[3][ITR][IT],
                                      float (&dst)[3][ITR][IT],
                                      const u64 (&wsp)[5][3][3][9],
                                      const u64 (&bsp)[5][3],
                                      int gy0, int gx0, int tid)
{
    constexpr int OFF = S + 1;
    constexpr int L   = 40 - 2*S;          // cols needed (= rows needed)
    constexpr int NG  = (L + 7) / 8;       // 8-row groups; items <= 200 <= NT
    if (tid < L*NG){
        const int col = OFF + tid % L;      // lanes -> consecutive cols: conflict-free
        int y = OFF + 8*(tid / L);
        if (y > ITR - 9) y = ITR - 9;       // clamp: reads y-1..y+8 stay in-bounds

        u64 A[3][4];
        #pragma unroll
        for (int o = 0; o < 3; o++){
            const u64 bb = bsp[S][o];
            #pragma unroll
            for (int t = 0; t < 4; t++) A[o][t] = bb;
        }

        #pragma unroll
        for (int i = 0; i < 3; i++){
            #pragma unroll
            for (int c = 0; c < 3; c++){
                float v[10];
                #pragma unroll
                for (int r = 0; r < 10; r++) v[r] = src[i][y-1+r][col-1+c];
                u64 P[9];
                #pragma unroll
                for (int j = 0; j < 9; j++) P[j] = pack2(v[j], v[j+1]);
                #pragma unroll
                for (int o = 0; o < 3; o++){
                    const u64 w0 = wsp[S][o][i][0*3 + c];   // broadcast LDS.64
                    const u64 w1 = wsp[S][o][i][1*3 + c];
                    const u64 w2 = wsp[S][o][i][2*3 + c];
                    #pragma unroll
                    for (int t = 0; t < 4; t++){
                        A[o][t] = fma2(w0, P[2*t],   A[o][t]);
                        A[o][t] = fma2(w1, P[2*t+1], A[o][t]);
                        A[o][t] = fma2(w2, P[2*t+2], A[o][t]);
                    }
                }
            }
        }

        const int gx = gx0 + col;
        #pragma unroll
        for (int o = 0; o < 3; o++){
            #pragma unroll
            for (int t = 0; t < 4; t++){
                const int y0 = y + 2*t;
                float lo, hi; unpack2(A[o][t], lo, hi);
                lo = lk(lo + src[o][y0  ][col]);
                hi = lk(hi + src[o][y0+1][col]);
                if (EDGE){
                    const int gy = gy0 + y0;
                    if (!(((unsigned)gy     < (unsigned)HI) && ((unsigned)gx < (unsigned)WI))) lo = 0.f;
                    if (!(((unsigned)(gy+1) < (unsigned)HI) && ((unsigned)gx < (unsigned)WI))) hi = 0.f;
                }
                dst[o][y0  ][col] = lo;
                dst[o][y0+1][col] = hi;
            }
        }
    }
}

__device__ __forceinline__ float att_eval(const float* c, float h, float w, float xi)
{
    float Ah = fmaf(h, fmaf(c[0],h, fmaf(c[1],w, fmaf(c[2],xi,c[3]))),
               fmaf(w, fmaf(c[4],w, fmaf(c[5],xi,c[6])),
               fmaf(xi, fmaf(c[7],xi,c[8]), c[9])));
    float Bw = fmaf(w, fmaf(c[10],w, fmaf(c[11],xi,c[12])),
               fmaf(xi, fmaf(c[13],xi,c[14]), c[15]));
    float Cx = fmaf(xi, fmaf(c[16],xi,c[17]), c[18]);
    return fmaf(h, Ah, fmaf(w, Bw, fmaf(xi, Cx, c[19])));
}

template<bool EDGE>
__device__ __forceinline__ void run_stages(SM& sm, int gy0, int gx0, int tid)
{
    stage<0,EDGE>(sm.a, sm.b, sm.wsp, sm.bsp, gy0, gx0, tid); __syncthreads();
    stage<1,EDGE>(sm.b, sm.a, sm.wsp, sm.bsp, gy0, gx0, tid); __syncthreads();
    stage<2,EDGE>(sm.a, sm.b, sm.wsp, sm.bsp, gy0, gx0, tid); __syncthreads();
    stage<3,EDGE>(sm.b, sm.a, sm.wsp, sm.bsp, gy0, gx0, tid); __syncthreads();
    stage<4,EDGE>(sm.a, sm.b, sm.wsp, sm.bsp, gy0, gx0, tid); __syncthreads();
}

__global__ __launch_bounds__(NT, 2)
void fused_kernel(const float* __restrict__ x,
                  const float* __restrict__ feature,
                  float* __restrict__ out)
{
    __shared__ SM sm;

    const int tile   = blockIdx.x;       // 0..1023
    const int bidx   = blockIdx.y;       // 0..7
    const int tilesX = WI / TS;          // 32
    const int ty = tile / tilesX, tx = tile % tilesX;
    const int gy0 = ty*TS - HALO, gx0 = tx*TS - HALO;
    const int tid = threadIdx.x;
    const bool edge = (ty == 0) | (ty == tilesX-1) | (tx == 0) | (tx == tilesX-1);

    // feature -> splatted conv weights / biases + tail
    const float* fb = feature + bidx*492;
    for (int idx = tid; idx < 5*84; idx += NT){
        int s = idx / 84, j = idx % 84;
        float f = fb[s*84 + j];
        if (j < 81){
            int o = j / 27, i = (j % 27) / 9, t = j % 9;
            sm.wsp[s][o][i][t] = pack2(f, f);
        } else {
            sm.bsp[s][j-81] = pack2(f, f);
        }
    }
    for (int idx = tid; idx < 72; idx += NT) sm.ftail[idx] = fb[420 + idx];

    // zero the two overhang rows of both buffers (rows 42,43)
    for (int idx = tid; idx < 3*2*IT; idx += NT){
        int cch = idx / (2*IT);
        int rr  = (idx / IT) % 2;
        int cc  = idx % IT;
        sm.a[cch][IT + rr][cc] = 0.f;
        sm.b[cch][IT + rr][cc] = 0.f;
    }

    // input tile (zero-padded at image boundary) -> smem A rows 0..41
    const float* xb = x + (size_t)bidx*3*HW;
    for (int p = tid; p < 3*IT*IT; p += NT){
        int cch = p / (IT*IT);
        int r   = p % (IT*IT);
        int yy = r / IT, xx = r % IT;            // lanes -> xx: coalesced LDG
        int gy = gy0 + yy, gx = gx0 + xx;
        float v = 0.f;
        if (((unsigned)gy < (unsigned)HI) && ((unsigned)gx < (unsigned)WI))
            v = xb[(size_t)cch*HW + (size_t)gy*WI + gx];
        sm.a[cch][yy][xx] = v;
    }
    __syncthreads();

    if (edge) run_stages<true >(sm, gy0, gx0, tid);
    else      run_stages<false>(sm, gy0, gx0, tid);
    // result in sm.b, valid rows/cols [HALO, HALO+TS)

    float k1[9], b1[3];
    #pragma unroll
    for (int j = 0; j < 9; j++) k1[j] = sm.ftail[j];
    #pragma unroll
    for (int o = 0; o < 3; o++) b1[o] = sm.ftail[9 + o];
    float ca[20], cb[20], cc[20];
    #pragma unroll
    for (int j = 0; j < 20; j++){
        ca[j] = sm.ftail[12 + j];
        cb[j] = sm.ftail[32 + j];
        cc[j] = sm.ftail[52 + j];
    }

    const float invH = 1.0f / HI, invW = 1.0f / WI;
    for (int p = tid; p < TS*TS; p += NT){
        int y  = HALO + p / TS;
        int xq = HALO + p % TS;
        int gy = gy0 + y, gx = gx0 + xq;

        float v0 = sm.b[0][y][xq];
        float v1 = sm.b[1][y][xq];
        float v2 = sm.b[2][y][xq];

        float t0 = lk(v0 + k1[0]*v0 + k1[1]*v1 + k1[2]*v2 + b1[0]);
        float t1 = lk(v1 + k1[3]*v0 + k1[4]*v1 + k1[5]*v2 + b1[1]);
        float t2 = lk(v2 + k1[6]*v0 + k1[7]*v1 + k1[8]*v2 + b1[2]);

        size_t pix = (size_t)gy*WI + gx;
        float xf0 = xb[pix]        + t0;   // global residual (original x)
        float xf1 = xb[HW + pix]   + t1;
        float xf2 = xb[2*HW + pix] + t2;

        float h  = (float)gy * invH;
        float w_ = (float)gx * invW;

        size_t base = (size_t)bidx*3*HW + pix;
        out[base]        = fmaf(xf0, att_eval(ca, h, w_, xf0), xf0);
        out[base + HW]   = fmaf(xf1, att_eval(cb, h, w_, xf1), xf1);
        out[base + 2*HW] = fmaf(xf2, att_eval(cc, h, w_, xf2), xf2);
    }
}

__global__ void copy_thumb_kernel(const float4* __restrict__ src, float4* __restrict__ dst)
{
    int i = blockIdx.x * blockDim.x + threadIdx.x;
    if (i < NTHUMB/4) dst[i] = src[i];
}

extern "C" void kernel_launch(void* const* d_in, const int* in_sizes, int n_in,
                              void* d_out, int out_size)
{
    const float* x     = (const float*)d_in[0];
    const float* thumb = (const float*)d_in[1];
    const float* feat  = (const float*)d_in[2];
    float* out = (float*)d_out;

    // thumb copy FIRST so ncu's skip-5 sample lands on fused_kernel
    int nv4 = NTHUMB/4;
    copy_thumb_kernel<<<(nv4 + 255)/256, 256>>>((const float4*)thumb,
                                                (float4*)(out + NPIX));

    dim3 grid((HI/TS)*(WI/TS), 8);
    fused_kernel<<<grid, NT>>>(x, feat, out);
}

// round 10
// speedup vs baseline: 1.3428x; 1.3428x over previous
#include <cuda_runtime.h>

#define TS 32
#define HALO 5
#define IT 42                 // cols per tile buffer
#define ITR 44                // rows padded for 4-row-group overhang
#define NT 416
#define HI 1024
#define WI 1024
#define HW (HI*WI)
#define NPIX (8*3*HW)         // 25165824
#define NTHUMB (8*3*256*256)  // 1572864

typedef unsigned long long u64;

__device__ __forceinline__ u64 pack2(float lo, float hi){
    u64 d;
    asm("mov.b64 %0, {%1, %2};" : "=l"(d)
        : "r"(__float_as_uint(lo)), "r"(__float_as_uint(hi)));
    return d;
}
__device__ __forceinline__ void unpack2(u64 v, float &lo, float &hi){
    unsigned a, b;
    asm("mov.b64 {%0, %1}, %2;" : "=r"(a), "=r"(b) : "l"(v));
    lo = __uint_as_float(a); hi = __uint_as_float(b);
}
__device__ __forceinline__ u64 fma2(u64 a, u64 b, u64 c){
    u64 d;
    asm("fma.rn.f32x2 %0, %1, %2, %3;" : "=l"(d) : "l"(a), "l"(b), "l"(c));
    return d;
}
__device__ __forceinline__ float lk(float v){ return fmaxf(v, 0.2f*v); } // exact leaky

struct SM {
    float a[3][ITR][IT];      // [ch][row][col] 22176 B
    float b[3][ITR][IT];      //                22176 B
    u64   wsp[5][3][3][9];    // splatted conv3 weights {w,w} [S][o][i][kh*3+kw]
    u64   bsp[5][3];          // splatted biases
    float ftail[72];          // feat[420..491]
};                            // 47904 B static

// One residual 3x3 block: dst = leaky(src + conv3x3(src)), zero-masked to image.
// Thread owns a 1-col x 4-row strip = 2 vertical f32x2 pairs. Column-streaming
// inner keeps the live register set small (~50). Items <= 400 <= NT: every
// stage is a single wave -> no barrier stragglers.
template<int S, bool EDGE>
__device__ __forceinline__ void stage(const float (&src)[3][ITR][IT],
                                      float (&dst)[3][ITR][IT],
                                      const u64 (&wsp)[5][3][3][9],
                                      const u64 (&bsp)[5][3],
                                      int gy0, int gx0, int tid)
{
    constexpr int OFF = S + 1;
    constexpr int L   = 40 - 2*S;          // rows/cols needed: 40,38,36,34,32
    constexpr int RG  = (L + 3) / 4;       // 4-row groups; items = L*RG <= 400
    if (tid < L*RG){
        const int col = OFF + tid % L;      // lanes -> consecutive cols: conflict-free
        const int y   = OFF + 4*(tid / L);  // overhang rows < ITR, provably unread

        u64 A[3][2];
        #pragma unroll
        for (int o = 0; o < 3; o++){ A[o][0] = bsp[S][o]; A[o][1] = bsp[S][o]; }

        #pragma unroll
        for (int i = 0; i < 3; i++){
            #pragma unroll
            for (int c = 0; c < 3; c++){
                float v0 = src[i][y-1][col-1+c];
                float v1 = src[i][y  ][col-1+c];
                float v2 = src[i][y+1][col-1+c];
                float v3 = src[i][y+2][col-1+c];
                float v4 = src[i][y+3][col-1+c];
                float v5 = src[i][y+4][col-1+c];
                u64 P0 = pack2(v0, v1);
                u64 P1 = pack2(v1, v2);
                u64 P2 = pack2(v2, v3);
                u64 P3 = pack2(v3, v4);
                u64 P4 = pack2(v4, v5);
                #pragma unroll
                for (int o = 0; o < 3; o++){
                    const u64 w0 = wsp[S][o][i][0*3 + c];   // broadcast LDS.64
                    const u64 w1 = wsp[S][o][i][1*3 + c];
                    const u64 w2 = wsp[S][o][i][2*3 + c];
                    A[o][0] = fma2(w0, P0, A[o][0]);
                    A[o][0] = fma2(w1, P1, A[o][0]);
                    A[o][0] = fma2(w2, P2, A[o][0]);
                    A[o][1] = fma2(w0, P2, A[o][1]);
                    A[o][1] = fma2(w1, P3, A[o][1]);
                    A[o][1] = fma2(w2, P4, A[o][1]);
                }
            }
        }

        const int gx = gx0 + col;
        #pragma unroll
        for (int o = 0; o < 3; o++){
            #pragma unroll
            for (int pp = 0; pp < 2; pp++){
                const int y0 = y + 2*pp;
                float lo, hi; unpack2(A[o][pp], lo, hi);
                lo = lk(lo + src[o][y0  ][col]);
                hi = lk(hi + src[o][y0+1][col]);
                if (EDGE){
                    const int gy = gy0 + y0;
                    if (!(((unsigned)gy     < (unsigned)HI) && ((unsigned)gx < (unsigned)WI))) lo = 0.f;
                    if (!(((unsigned)(gy+1) < (unsigned)HI) && ((unsigned)gx < (unsigned)WI))) hi = 0.f;
                }
                dst[o][y0  ][col] = lo;
                dst[o][y0+1][col] = hi;
            }
        }
    }
}

__device__ __forceinline__ float att_eval(const float* c, float h, float w, float xi)
{
    float Ah = fmaf(h, fmaf(c[0],h, fmaf(c[1],w, fmaf(c[2],xi,c[3]))),
               fmaf(w, fmaf(c[4],w, fmaf(c[5],xi,c[6])),
               fmaf(xi, fmaf(c[7],xi,c[8]), c[9])));
    float Bw = fmaf(w, fmaf(c[10],w, fmaf(c[11],xi,c[12])),
               fmaf(xi, fmaf(c[13],xi,c[14]), c[15]));
    float Cx = fmaf(xi, fmaf(c[16],xi,c[17]), c[18]);
    return fmaf(h, Ah, fmaf(w, Bw, fmaf(xi, Cx, c[19])));
}

template<bool EDGE>
__device__ __forceinline__ void run_stages(SM& sm, int gy0, int gx0, int tid)
{
    stage<0,EDGE>(sm.a, sm.b, sm.wsp, sm.bsp, gy0, gx0, tid); __syncthreads();
    stage<1,EDGE>(sm.b, sm.a, sm.wsp, sm.bsp, gy0, gx0, tid); __syncthreads();
    stage<2,EDGE>(sm.a, sm.b, sm.wsp, sm.bsp, gy0, gx0, tid); __syncthreads();
    stage<3,EDGE>(sm.b, sm.a, sm.wsp, sm.bsp, gy0, gx0, tid); __syncthreads();
    stage<4,EDGE>(sm.a, sm.b, sm.wsp, sm.bsp, gy0, gx0, tid); __syncthreads();
}

__global__ __launch_bounds__(NT, 2)
void fused_kernel(const float* __restrict__ x,
                  const float* __restrict__ feature,
                  float* __restrict__ out)
{
    __shared__ SM sm;

    const int tile   = blockIdx.x;       // 0..1023
    const int bidx   = blockIdx.y;       // 0..7
    const int tilesX = WI / TS;          // 32
    const int ty = tile / tilesX, tx = tile % tilesX;
    const int gy0 = ty*TS - HALO, gx0 = tx*TS - HALO;
    const int tid = threadIdx.x;
    const bool edge = (ty == 0) | (ty == tilesX-1) | (tx == 0) | (tx == tilesX-1);

    // feature -> splatted conv weights / biases + tail
    const float* fb = feature + bidx*492;
    for (int idx = tid; idx < 5*84; idx += NT){
        int s = idx / 84, j = idx % 84;
        float f = fb[s*84 + j];
        if (j < 81){
            int o = j / 27, i = (j % 27) / 9, t = j % 9;
            sm.wsp[s][o][i][t] = pack2(f, f);
        } else {
            sm.bsp[s][j-81] = pack2(f, f);
        }
    }
    for (int idx = tid; idx < 72; idx += NT) sm.ftail[idx] = fb[420 + idx];

    // input tile (zero-padded at image boundary) -> smem A rows 0..41
    const float* xb = x + (size_t)bidx*3*HW;
    for (int p = tid; p < 3*IT*IT; p += NT){
        int cch = p / (IT*IT);
        int r   = p % (IT*IT);
        int yy = r / IT, xx = r % IT;            // lanes -> xx: coalesced LDG
        int gy = gy0 + yy, gx = gx0 + xx;
        float v = 0.f;
        if (((unsigned)gy < (unsigned)HI) && ((unsigned)gx < (unsigned)WI))
            v = xb[(size_t)cch*HW + (size_t)gy*WI + gx];
        sm.a[cch][yy][xx] = v;
    }
    __syncthreads();

    if (edge) run_stages<true >(sm, gy0, gx0, tid);
    else      run_stages<false>(sm, gy0, gx0, tid);
    // result in sm.b, valid rows/cols [HALO, HALO+TS)

    float k1[9], b1[3];
    #pragma unroll
    for (int j = 0; j < 9; j++) k1[j] = sm.ftail[j];
    #pragma unroll
    for (int o = 0; o < 3; o++) b1[o] = sm.ftail[9 + o];
    float ca[20], cb[20], cc[20];
    #pragma unroll
    for (int j = 0; j < 20; j++){
        ca[j] = sm.ftail[12 + j];
        cb[j] = sm.ftail[32 + j];
        cc[j] = sm.ftail[52 + j];
    }

    const float invH = 1.0f / HI, invW = 1.0f / WI;
    for (int p = tid; p < TS*TS; p += NT){
        int y  = HALO + p / TS;
        int xq = HALO + p % TS;
        int gy = gy0 + y, gx = gx0 + xq;

        float v0 = sm.b[0][y][xq];
        float v1 = sm.b[1][y][xq];
        float v2 = sm.b[2][y][xq];

        float t0 = lk(v0 + k1[0]*v0 + k1[1]*v1 + k1[2]*v2 + b1[0]);
        float t1 = lk(v1 + k1[3]*v0 + k1[4]*v1 + k1[5]*v2 + b1[1]);
        float t2 = lk(v2 + k1[6]*v0 + k1[7]*v1 + k1[8]*v2 + b1[2]);

        size_t pix = (size_t)gy*WI + gx;
        float xf0 = xb[pix]        + t0;   // global residual (original x)
        float xf1 = xb[HW + pix]   + t1;
        float xf2 = xb[2*HW + pix] + t2;

        float h  = (float)gy * invH;
        float w_ = (float)gx * invW;

        size_t base = (size_t)bidx*3*HW + pix;
        out[base]        = fmaf(xf0, att_eval(ca, h, w_, xf0), xf0);
        out[base + HW]   = fmaf(xf1, att_eval(cb, h, w_, xf1), xf1);
        out[base + 2*HW] = fmaf(xf2, att_eval(cc, h, w_, xf2), xf2);
    }
}

__global__ void copy_thumb_kernel(const float4* __restrict__ src, float4* __restrict__ dst)
{
    int i = blockIdx.x * blockDim.x + threadIdx.x;
    if (i < NTHUMB/4) dst[i] = src[i];
}

extern "C" void kernel_launch(void* const* d_in, const int* in_sizes, int n_in,
                              void* d_out, int out_size)
{
    const float* x     = (const float*)d_in[0];
    const float* thumb = (const float*)d_in[1];
    const float* feat  = (const float*)d_in[2];
    float* out = (float*)d_out;

    // thumb copy FIRST so ncu's skip-5 sample lands on fused_kernel
    int nv4 = NTHUMB/4;
    copy_thumb_kernel<<<(nv4 + 255)/256, 256>>>((const float4*)thumb,
                                                (float4*)(out + NPIX));

    dim3 grid((HI/TS)*(WI/TS), 8);
    fused_kernel<<<grid, NT>>>(x, feat, out);
}

// round 11
// speedup vs baseline: 1.7749x; 1.3218x over previous
#include <cuda_runtime.h>

#define TS 32
#define HALO 5
#define IT 42                 // TS + 2*HALO (cols)
#define ITR 44                // rows padded for 4-row-group overhang reads
#define NT 256
#define HI 1024
#define WI 1024
#define HW (HI*WI)
#define NPIX (8*3*HW)         // 25165824
#define NTHUMB (8*3*256*256)  // 1572864

typedef unsigned long long u64;

__device__ __forceinline__ u64 pack2(float lo, float hi){
    u64 d;
    asm("mov.b64 %0, {%1, %2};" : "=l"(d)
        : "r"(__float_as_uint(lo)), "r"(__float_as_uint(hi)));
    return d;
}
__device__ __forceinline__ void unpack2(u64 v, float &lo, float &hi){
    unsigned a, b;
    asm("mov.b64 {%0, %1}, %2;" : "=r"(a), "=r"(b) : "l"(v));
    lo = __uint_as_float(a); hi = __uint_as_float(b);
}
__device__ __forceinline__ u64 fma2(u64 a, u64 b, u64 c){
    u64 d;
    asm("fma.rn.f32x2 %0, %1, %2, %3;" : "=l"(d) : "l"(a), "l"(b), "l"(c));
    return d;
}

__device__ __forceinline__ float lk(float v){ return fmaxf(v, 0.2f*v); }  // exact leaky, slope in (0,1)

struct SM {
    float a[3][ITR][IT];      // 22176 B
    float b[3][ITR][IT];      // 22176 B
    u64   wsp[5][3][3][9];    // splatted conv3 weights {w,w}: 3240 B
    u64   bsp[5][3];          // splatted biases: 120 B
    float ftail[72];          // feat[420..491]: 1x1 weights + att coefs
};                            // total ~47.9 KB

// One residual 3x3 block: dst = leaky(src + conv3x3(src)), zero-masked to image.
// Each thread handles a 4x1 vertical pixel strip = 2 packed f32x2 pairs.
// Batched loads (18 independent LDS per input channel) let ptxas pipeline
// against LDS latency — this schedule is the measured winner.
template<int S, bool EDGE>
__device__ __forceinline__ void stage(const float (&src)[3][ITR][IT],
                                      float (&dst)[3][ITR][IT],
                                      const u64 (&wsp)[5][3][3][9],
                                      const u64 (&bsp)[5][3],
                                      int gy0, int gx0, int tid)
{
    constexpr int OFF = S + 1;
    constexpr int L   = IT - 2*OFF;       // 40,38,36,34,32
    constexpr int RG  = (L + 3) / 4;      // 4-row groups (overhang rows land in unread region)
    for (int p = tid; p < L*RG; p += NT){
        const int col = OFF + p % L;       // lanes -> consecutive cols: conflict-free LDS
        const int y   = OFF + 4*(p / L);
        u64 A[3][2];
        #pragma unroll
        for (int o = 0; o < 3; o++){ A[o][0] = bsp[S][o]; A[o][1] = bsp[S][o]; }

        #pragma unroll
        for (int i = 0; i < 3; i++){
            float v[3][6];
            #pragma unroll
            for (int c = 0; c < 3; c++)
                #pragma unroll
                for (int r = 0; r < 6; r++)
                    v[c][r] = src[i][y-1+r][col-1+c];
            u64 P[3][5];                    // vertical pairs {v[j], v[j+1]}
            #pragma unroll
            for (int c = 0; c < 3; c++)
                #pragma unroll
                for (int j = 0; j < 5; j++)
                    P[c][j] = pack2(v[c][j], v[c][j+1]);
            #pragma unroll
            for (int o = 0; o < 3; o++){
                #pragma unroll
                for (int kh = 0; kh < 3; kh++)
                    #pragma unroll
                    for (int kw = 0; kw < 3; kw++){
                        u64 w2 = wsp[S][o][i][kh*3+kw];      // broadcast LDS.64
                        A[o][0] = fma2(w2, P[kw][kh],   A[o][0]);
                        A[o][1] = fma2(w2, P[kw][kh+2], A[o][1]);
                    }
            }
        }

        const int gx = gx0 + col;
        #pragma unroll
        for (int o = 0; o < 3; o++){
            #pragma unroll
            for (int pp = 0; pp < 2; pp++){
                const int y0 = y + 2*pp;
                float r0 = src[o][y0][col], r1 = src[o][y0+1][col];
                float lo, hi; unpack2(A[o][pp], lo, hi);
                lo = lk(lo + r0);
                hi = lk(hi + r1);
                if (EDGE){
                    int gy = gy0 + y0;
                    bool in0 = ((unsigned)gy     < (unsigned)HI) && ((unsigned)gx < (unsigned)WI);
                    bool in1 = ((unsigned)(gy+1) < (unsigned)HI) && ((unsigned)gx < (unsigned)WI);
                    lo = in0 ? lo : 0.f;
                    hi = in1 ? hi : 0.f;
                }
                dst[o][y0][col]   = lo;
                dst[o][y0+1][col] = hi;
            }
        }
    }
}

__device__ __forceinline__ float att_eval(const float* c, float h, float w, float xi)
{
    float h2 = h*h,  h3 = h2*h;
    float w2 = w*w,  w3 = w2*w;
    float x2 = xi*xi, x3 = x2*xi;
    return c[0]*h3 + c[1]*(h2*w) + c[2]*(h2*xi) + c[3]*h2 + c[4]*(h*w2)
         + c[5]*(h*w*xi) + c[6]*(h*w) + c[7]*(h*x2) + c[8]*(h*xi) + c[9]*h
         + c[10]*w3 + c[11]*(w2*xi) + c[12]*w2 + c[13]*(w*x2) + c[14]*(w*xi)
         + c[15]*w + c[16]*x3 + c[17]*x2 + c[18]*xi + c[19];
}

template<bool EDGE>
__device__ __forceinline__ void run_stages(SM& sm, int gy0, int gx0, int tid)
{
    stage<0,EDGE>(sm.a, sm.b, sm.wsp, sm.bsp, gy0, gx0, tid); __syncthreads();
    stage<1,EDGE>(sm.b, sm.a, sm.wsp, sm.bsp, gy0, gx0, tid); __syncthreads();
    stage<2,EDGE>(sm.a, sm.b, sm.wsp, sm.bsp, gy0, gx0, tid); __syncthreads();
    stage<3,EDGE>(sm.b, sm.a, sm.wsp, sm.bsp, gy0, gx0, tid); __syncthreads();
    stage<4,EDGE>(sm.a, sm.b, sm.wsp, sm.bsp, gy0, gx0, tid); __syncthreads();
}

__global__ __launch_bounds__(NT, 3)
void fused_kernel(const float* __restrict__ x,
                  const float* __restrict__ feature,
                  float* __restrict__ out)
{
    __shared__ SM sm;

    const int tile   = blockIdx.x;       // 0..1023
    const int bidx   = blockIdx.y;       // 0..7
    const int tilesX = WI / TS;          // 32
    const int ty = tile / tilesX, tx = tile % tilesX;
    const int gy0 = ty*TS - HALO, gx0 = tx*TS - HALO;
    const int tid = threadIdx.x;
    const bool edge = (ty == 0) | (ty == tilesX-1) | (tx == 0) | (tx == tilesX-1);

    // feature -> splatted conv weights / biases + tail
    const float* fb = feature + bidx*492;
    for (int idx = tid; idx < 5*84; idx += NT){
        int s = idx / 84, j = idx % 84;
        float f = fb[s*84 + j];
        if (j < 81){
            int o = j / 27, i = (j % 27) / 9, t = j % 9;
            sm.wsp[s][o][i][t] = pack2(f, f);
        } else {
            sm.bsp[s][j-81] = pack2(f, f);
        }
    }
    for (int idx = tid; idx < 72; idx += NT) sm.ftail[idx] = fb[420 + idx];

    // input tile (zero-padded at image boundary) -> smem A (rows 0..41)
    const float* xb = x + (size_t)bidx*3*HW;
    for (int p = tid; p < 3*IT*IT; p += NT){
        int c  = p / (IT*IT);
        int r  = p % (IT*IT);
        int yy = r / IT, xx = r % IT;
        int gy = gy0 + yy, gx = gx0 + xx;
        float v = 0.f;
        if (((unsigned)gy < (unsigned)HI) && ((unsigned)gx < (unsigned)WI))
            v = xb[(size_t)c*HW + (size_t)gy*WI + gx];
        sm.a[c][yy][xx] = v;
    }
    __syncthreads();

    if (edge) run_stages<true >(sm, gy0, gx0, tid);
    else      run_stages<false>(sm, gy0, gx0, tid);
    // result in sm.b on [HALO, HALO+TS)^2

    float k1[9], b1[3];
    #pragma unroll
    for (int j = 0; j < 9; j++) k1[j] = sm.ftail[j];
    #pragma unroll
    for (int o = 0; o < 3; o++) b1[o] = sm.ftail[9 + o];
    float ca[20], cb[20], cc[20];
    #pragma unroll
    for (int j = 0; j < 20; j++){
        ca[j] = sm.ftail[12 + j];
        cb[j] = sm.ftail[32 + j];
        cc[j] = sm.ftail[52 + j];
    }

    const float invH = 1.0f / HI, invW = 1.0f / WI;
    for (int p = tid; p < TS*TS; p += NT){
        int y  = HALO + p / TS;
        int xq = HALO + p % TS;
        int gy = gy0 + y, gx = gx0 + xq;

        float v0 = sm.b[0][y][xq];
        float v1 = sm.b[1][y][xq];
        float v2 = sm.b[2][y][xq];

        float t0 = lk(v0 + k1[0]*v0 + k1[1]*v1 + k1[2]*v2 + b1[0]);
        float t1 = lk(v1 + k1[3]*v0 + k1[4]*v1 + k1[5]*v2 + b1[1]);
        float t2 = lk(v2 + k1[6]*v0 + k1[7]*v1 + k1[8]*v2 + b1[2]);

        size_t pix = (size_t)gy*WI + gx;
        float xf0 = xb[pix]        + t0;   // global residual (original x)
        float xf1 = xb[HW + pix]   + t1;
        float xf2 = xb[2*HW + pix] + t2;

        float h  = (float)gy * invH;
        float w_ = (float)gx * invW;

        size_t base = (size_t)bidx*3*HW + pix;
        out[base]        = fmaf(xf0, att_eval(ca, h, w_, xf0), xf0);
        out[base + HW]   = fmaf(xf1, att_eval(cb, h, w_, xf1), xf1);
        out[base + 2*HW] = fmaf(xf2, att_eval(cc, h, w_, xf2), xf2);
    }
}

__global__ void copy_thumb_kernel(const float4* __restrict__ src, float4* __restrict__ dst)
{
    int i = blockIdx.x * blockDim.x + threadIdx.x;
    if (i < NTHUMB/4) dst[i] = src[i];
}

extern "C" void kernel_launch(void* const* d_in, const int* in_sizes, int n_in,
                              void* d_out, int out_size)
{
    const float* x     = (const float*)d_in[0];
    const float* thumb = (const float*)d_in[1];
    const float* feat  = (const float*)d_in[2];
    float* out = (float*)d_out;

    // thumb copy FIRST so ncu's skip-5 sample lands on fused_kernel
    int nv4 = NTHUMB/4;
    copy_thumb_kernel<<<(nv4 + 255)/256, 256>>>((const float4*)thumb,
                                                (float4*)(out + NPIX));

    dim3 grid((HI/TS)*(WI/TS), 8);
    fused_kernel<<<grid, NT>>>(x, feat, out);
}